// round 8
// baseline (speedup 1.0000x reference)
#include <cuda_runtime.h>
#include <cuda_bf16.h>
#include <cstdint>

// ---------------------------------------------------------------------------
// LastAggregator: out[n, :] = msg[argmax_{i : index[i]==n} t[i], :]
// (ties -> smallest i; empty segments -> zeros)
//
//   key(i) = (total_order(t[i]) << 32) | ~i    packed into u64
//   atomicMax over keys per segment  ->  winner = ~(low 32 bits)
//   key == 0  <=>  empty segment (valid keys have nonzero low word).
//
// Self-cleaning: the gather kernel resets each consumed key to 0, so no
// separate init pass is needed (device globals start zero-initialized,
// and every call leaves the array cleared -> identical work per call).
//
// index arrives as int32 (JAX x64 disabled downcasts the declared int64).
// ---------------------------------------------------------------------------

#define MAX_SEGMENTS (1 << 17)  // 131072 >= N = 65536
__device__ unsigned long long g_key[MAX_SEGMENTS];

__device__ __forceinline__ void stcs_f4(float4* p, float4 v) {
    // streaming store: write-once output, evict-first so it never displaces
    // the winner rows from L2
    asm volatile("st.global.cs.v4.f32 [%0], {%1,%2,%3,%4};"
                 :: "l"(p), "f"(v.x), "f"(v.y), "f"(v.z), "f"(v.w) : "memory");
}

// 256-bit load with L2 evict-last (sm_103a requires v8.b32 for this hint).
// Pins the re-read winner rows in L2 across graph replays.
__device__ __forceinline__ void ldg256_el(const float* p, float4& a, float4& b) {
    unsigned int r0, r1, r2, r3, r4, r5, r6, r7;
    asm("ld.global.nc.L2::evict_last.v8.b32 {%0,%1,%2,%3,%4,%5,%6,%7}, [%8];"
        : "=r"(r0), "=r"(r1), "=r"(r2), "=r"(r3),
          "=r"(r4), "=r"(r5), "=r"(r6), "=r"(r7)
        : "l"(p));
    a = make_float4(__uint_as_float(r0), __uint_as_float(r1),
                    __uint_as_float(r2), __uint_as_float(r3));
    b = make_float4(__uint_as_float(r4), __uint_as_float(r5),
                    __uint_as_float(r6), __uint_as_float(r7));
}

__device__ __forceinline__ unsigned long long
make_key(float tv, unsigned int i) {
    unsigned int fb  = __float_as_uint(tv);
    unsigned int ord = (fb & 0x80000000u) ? ~fb : (fb | 0x80000000u);
    return ((unsigned long long)ord << 32) | (unsigned long long)(~i);
}

// --- argmax: 4 events per thread, vectorized loads --------------------------
__global__ void la_argmax_kernel(const int* __restrict__ index,
                                 const float* __restrict__ t,
                                 int M, int N) {
    int base = (blockIdx.x * blockDim.x + threadIdx.x) * 4;
    if (base + 3 < M) {
        int4   s  = *reinterpret_cast<const int4*>(index + base);
        float4 tv = *reinterpret_cast<const float4*>(t + base);
        int   segs[4] = {s.x, s.y, s.z, s.w};
        float ts[4]   = {tv.x, tv.y, tv.z, tv.w};
#pragma unroll
        for (int k = 0; k < 4; ++k) {
            unsigned long long key = make_key(ts[k], (unsigned int)(base + k));
            int seg = segs[k];
            if (seg >= 0 && seg < N) atomicMax(&g_key[seg], key);  // -> REDG
        }
    } else {
        for (int i = base; i < M; ++i) {
            unsigned long long key = make_key(t[i], (unsigned int)i);
            int seg = index[i];
            if (seg >= 0 && seg < N) atomicMax(&g_key[seg], key);
        }
    }
}

// --- D=256 gather: one warp per 2 rows; 256-bit loads; self-cleans keys -----
// Each thread: 2 independent LDG.256 chains + 4 STG.128.
// Thread lane covers floats [lane*8, lane*8+8) of each row (fully coalesced).
__global__ void la_gather_d256_kernel(const float* __restrict__ msg,
                                      float4* __restrict__ out,
                                      int N) {
    int gwarp = (blockIdx.x * blockDim.x + threadIdx.x) >> 5;
    int lane  = threadIdx.x & 31;
    int r0 = gwarp * 2;
    int r1 = r0 + 1;
    if (r0 >= N) return;
    bool has1 = (r1 < N);

    // lanes 0/1 fetch the two keys in parallel, broadcast to all lanes
    unsigned long long kk = 0ull;
    if (lane == 0)              kk = g_key[r0];
    else if (lane == 1 && has1) kk = g_key[r1];
    unsigned long long key0 = __shfl_sync(0xffffffffu, kk, 0);
    unsigned long long key1 = __shfl_sync(0xffffffffu, kk, 1);
    // self-clean for next call (after all lanes hold the values)
    if (lane == 0)              g_key[r0] = 0ull;
    else if (lane == 1 && has1) g_key[r1] = 0ull;

    const float4 z = make_float4(0.f, 0.f, 0.f, 0.f);
    int fo = lane * 8;                       // float offset within row

    float4 a0 = z, a1 = z, b0 = z, b1 = z;
    if (key0 != 0ull) {
        unsigned int win = ~(unsigned int)(key0 & 0xFFFFFFFFull);
        ldg256_el(msg + (size_t)win * 256 + fo, a0, a1);
    }
    if (has1 && key1 != 0ull) {
        unsigned int win = ~(unsigned int)(key1 & 0xFFFFFFFFull);
        ldg256_el(msg + (size_t)win * 256 + fo, b0, b1);
    }

    float4* o0 = &out[(size_t)r0 * 64 + lane * 2];
    stcs_f4(o0,     a0);
    stcs_f4(o0 + 1, a1);
    if (has1) {
        float4* o1 = &out[(size_t)r1 * 64 + lane * 2];
        stcs_f4(o1,     b0);
        stcs_f4(o1 + 1, b1);
    }
}

// --- generic fallback (unexpected D): init + argmax + gather ----------------
__global__ void la_init_kernel(int N) {
    int i = blockIdx.x * blockDim.x + threadIdx.x;
    if (i < N) g_key[i] = 0ull;
}

__global__ void la_gather_generic_kernel(const float4* __restrict__ msg,
                                         float4* __restrict__ out,
                                         int N, int D4) {
    long long e = (long long)blockIdx.x * blockDim.x + threadIdx.x;
    long long total = (long long)N * D4;
    if (e >= total) return;
    int row  = (int)(e / D4);
    int lane = (int)(e % D4);
    unsigned long long key = g_key[row];
    float4 v = make_float4(0.f, 0.f, 0.f, 0.f);
    if (key != 0ull) {
        unsigned int win = ~(unsigned int)(key & 0xFFFFFFFFull);
        v = __ldg(&msg[(size_t)win * D4 + lane]);
    }
    out[(size_t)row * D4 + lane] = v;
}

extern "C" void kernel_launch(void* const* d_in, const int* in_sizes, int n_in,
                              void* d_out, int out_size) {
    // metadata order: msg [M*D f32], index [M i32], t [M f32], (dim_size)
    const float* msg   = (const float*)d_in[0];
    const int*   index = (const int*)d_in[1];
    const float* t     = (const float*)d_in[2];
    float*       out   = (float*)d_out;

    int M = in_sizes[1];              // 262144
    int D = in_sizes[0] / M;          // 256
    int N = out_size / D;             // 65536
    if (N > MAX_SEGMENTS) N = MAX_SEGMENTS;

    if (D == 256) {
        {   // argmax: 4 events/thread
            int threads = 256;
            int per_blk = threads * 4;
            int blocks  = (M + per_blk - 1) / per_blk;
            la_argmax_kernel<<<blocks, threads>>>(index, t, M, N);
        }
        {   // gather: 2 rows per warp, 256-bit loads, self-cleaning
            int threads = 256;                     // 8 warps = 16 rows/block
            int rows_per_blk = (threads / 32) * 2;
            int blocks = (N + rows_per_blk - 1) / rows_per_blk;
            la_gather_d256_kernel<<<blocks, threads>>>(msg, (float4*)out, N);
        }
    } else {
        // generic safe path
        {
            int threads = 256;
            int blocks  = (N + threads - 1) / threads;
            la_init_kernel<<<blocks, threads>>>(N);
        }
        {
            int threads = 256;
            int per_blk = threads * 4;
            int blocks  = (M + per_blk - 1) / per_blk;
            la_argmax_kernel<<<blocks, threads>>>(index, t, M, N);
        }
        {
            int D4 = D / 4;
            long long total = (long long)N * D4;
            int threads = 256;
            int blocks  = (int)((total + threads - 1) / threads);
            la_gather_generic_kernel<<<blocks, threads>>>((const float4*)msg,
                                                          (float4*)out, N, D4);
        }
    }
}

// round 12
// speedup vs baseline: 1.0553x; 1.0553x over previous
#include <cuda_runtime.h>
#include <cuda_bf16.h>
#include <cstdint>

// ---------------------------------------------------------------------------
// LastAggregator: out[n, :] = msg[argmax_{i : index[i]==n} t[i], :]
// (ties -> smallest i; empty segments -> zeros)
//
//   key(i) = (total_order(t[i]) << 32) | ~i    packed into u64
//   atomicMax over keys per segment  ->  winner = ~(low 32 bits)
//   key == 0  <=>  empty segment (valid keys have nonzero low word).
//
// Fused persistent kernel: phase 1 (argmax) -> software grid barrier ->
// phase 2 (gather). Self-cleaning: phase 2 resets consumed keys to 0, so
// device-global zero-init covers call 1 and every call leaves state clean.
// Barrier: self-resetting arrive counter + monotonic generation flag with
// __nanosleep backoff (generation value never affects output).
//
// index arrives as int32 (JAX x64 disabled downcasts the declared int64).
// ---------------------------------------------------------------------------

#define MAX_SEGMENTS (1 << 17)  // 131072 >= N = 65536
__device__ unsigned long long g_key[MAX_SEGMENTS];
__device__ unsigned int g_bar_count;   // zero-init; self-resets each call
__device__ unsigned int g_bar_gen;     // monotonic across calls

#define FUSED_BLOCKS  288              // <= 2/SM on 148/152-SM parts
#define FUSED_THREADS 256

__device__ __forceinline__ void stcs_f4(float4* p, float4 v) {
    // streaming store: write-once output, evict-first in L2
    asm volatile("st.global.cs.v4.f32 [%0], {%1,%2,%3,%4};"
                 :: "l"(p), "f"(v.x), "f"(v.y), "f"(v.z), "f"(v.w) : "memory");
}

__device__ __forceinline__ unsigned long long ldcg_u64(const unsigned long long* p) {
    unsigned long long v;
    asm volatile("ld.global.cg.u64 %0, [%1];" : "=l"(v) : "l"(p) : "memory");
    return v;
}
__device__ __forceinline__ void stcg_u64(unsigned long long* p, unsigned long long v) {
    asm volatile("st.global.cg.u64 [%0], %1;" :: "l"(p), "l"(v) : "memory");
}

__device__ __forceinline__ unsigned long long
make_key(float tv, unsigned int i) {
    unsigned int fb  = __float_as_uint(tv);
    unsigned int ord = (fb & 0x80000000u) ? ~fb : (fb | 0x80000000u);
    return ((unsigned long long)ord << 32) | (unsigned long long)(~i);
}

// --- fused kernel (D == 256) ------------------------------------------------
__global__ void __launch_bounds__(FUSED_THREADS, 2)
la_fused_d256_kernel(const float4* __restrict__ msg,
                     const int*    __restrict__ index,
                     const float*  __restrict__ t,
                     float4*       __restrict__ out,
                     int M, int N) {
    const int tid      = blockIdx.x * blockDim.x + threadIdx.x;
    const int nthreads = gridDim.x * blockDim.x;

    // ---------------- phase 1: segment argmax (grid-stride, 4 events/step) --
    {
        int nvec = M >> 2;
        for (int v = tid; v < nvec; v += nthreads) {
            int base = v << 2;
            int4   s  = *reinterpret_cast<const int4*>(index + base);
            float4 tv = *reinterpret_cast<const float4*>(t + base);
            int   segs[4] = {s.x, s.y, s.z, s.w};
            float ts[4]   = {tv.x, tv.y, tv.z, tv.w};
#pragma unroll
            for (int k = 0; k < 4; ++k) {
                unsigned long long key = make_key(ts[k], (unsigned int)(base + k));
                int seg = segs[k];
                if (seg >= 0 && seg < N) atomicMax(&g_key[seg], key);
            }
        }
        for (int i = (M & ~3) + tid; i < M; i += nthreads) {
            unsigned long long key = make_key(t[i], (unsigned int)i);
            int seg = index[i];
            if (seg >= 0 && seg < N) atomicMax(&g_key[seg], key);
        }
    }

    // ---------------- grid barrier (sleep-backoff spin) ---------------------
    __syncthreads();
    if (threadIdx.x == 0) {
        unsigned int gen = *((volatile unsigned int*)&g_bar_gen);
        __threadfence();                       // publish phase-1 atomics
        if (atomicAdd(&g_bar_count, 1u) == gridDim.x - 1u) {
            g_bar_count = 0u;                  // all arrived; safe to reset
            __threadfence();
            atomicAdd(&g_bar_gen, 1u);         // release spinners
        } else {
            while (*((volatile unsigned int*)&g_bar_gen) == gen) {
                __nanosleep(64);
            }
        }
    }
    __syncthreads();

    // ---------------- phase 2: gather (2 rows per warp per iteration) -------
    const int gwarp      = tid >> 5;
    const int lane       = threadIdx.x & 31;
    const int totalWarps = nthreads >> 5;
    const float4 z = make_float4(0.f, 0.f, 0.f, 0.f);

    for (int r0 = gwarp * 2; r0 < N; r0 += totalWarps * 2) {
        int r1 = r0 + 1;
        bool has1 = (r1 < N);

        unsigned long long kk = 0ull;
        if (lane == 0)              kk = ldcg_u64(&g_key[r0]);
        else if (lane == 1 && has1) kk = ldcg_u64(&g_key[r1]);
        unsigned long long key0 = __shfl_sync(0xffffffffu, kk, 0);
        unsigned long long key1 = __shfl_sync(0xffffffffu, kk, 1);
        if (lane == 0)              stcg_u64(&g_key[r0], 0ull);   // self-clean
        else if (lane == 1 && has1) stcg_u64(&g_key[r1], 0ull);

        float4 a0 = z, a1 = z, b0 = z, b1 = z;
        if (key0 != 0ull) {
            size_t ib = (size_t)(~(unsigned int)(key0 & 0xFFFFFFFFull)) * 64;
            a0 = __ldg(&msg[ib + lane]);
            a1 = __ldg(&msg[ib + lane + 32]);
        }
        if (has1 && key1 != 0ull) {
            size_t ib = (size_t)(~(unsigned int)(key1 & 0xFFFFFFFFull)) * 64;
            b0 = __ldg(&msg[ib + lane]);
            b1 = __ldg(&msg[ib + lane + 32]);
        }
        size_t ob0 = (size_t)r0 * 64;
        stcs_f4(&out[ob0 + lane],      a0);
        stcs_f4(&out[ob0 + lane + 32], a1);
        if (has1) {
            size_t ob1 = (size_t)r1 * 64;
            stcs_f4(&out[ob1 + lane],      b0);
            stcs_f4(&out[ob1 + lane + 32], b1);
        }
    }
}

// --- generic fallback (unexpected D): init + argmax + gather ----------------
__global__ void la_init_kernel(int N) {
    int i = blockIdx.x * blockDim.x + threadIdx.x;
    if (i < N) g_key[i] = 0ull;
}

__global__ void la_argmax_kernel(const int* __restrict__ index,
                                 const float* __restrict__ t,
                                 int M, int N) {
    int i = blockIdx.x * blockDim.x + threadIdx.x;
    if (i >= M) return;
    unsigned long long key = make_key(t[i], (unsigned int)i);
    int seg = index[i];
    if (seg >= 0 && seg < N) atomicMax(&g_key[seg], key);
}

__global__ void la_gather_generic_kernel(const float4* __restrict__ msg,
                                         float4* __restrict__ out,
                                         int N, int D4) {
    long long e = (long long)blockIdx.x * blockDim.x + threadIdx.x;
    long long total = (long long)N * D4;
    if (e >= total) return;
    int row  = (int)(e / D4);
    int lane = (int)(e % D4);
    unsigned long long key = g_key[row];
    float4 v = make_float4(0.f, 0.f, 0.f, 0.f);
    if (key != 0ull) {
        unsigned int win = ~(unsigned int)(key & 0xFFFFFFFFull);
        v = __ldg(&msg[(size_t)win * D4 + lane]);
    }
    out[(size_t)row * D4 + lane] = v;
    if (lane == 0) stcg_u64(&g_key[row], 0ull);
}

extern "C" void kernel_launch(void* const* d_in, const int* in_sizes, int n_in,
                              void* d_out, int out_size) {
    // metadata order: msg [M*D f32], index [M i32], t [M f32], (dim_size)
    const float* msg   = (const float*)d_in[0];
    const int*   index = (const int*)d_in[1];
    const float* t     = (const float*)d_in[2];
    float*       out   = (float*)d_out;

    int M = in_sizes[1];              // 262144
    int D = in_sizes[0] / M;          // 256
    int N = out_size / D;             // 65536
    if (N > MAX_SEGMENTS) N = MAX_SEGMENTS;

    if (D == 256) {
        la_fused_d256_kernel<<<FUSED_BLOCKS, FUSED_THREADS>>>(
            (const float4*)msg, index, t, (float4*)out, M, N);
    } else {
        // generic safe path
        {
            int threads = 256;
            int blocks  = (N + threads - 1) / threads;
            la_init_kernel<<<blocks, threads>>>(N);
        }
        {
            int threads = 256;
            int blocks  = (M + threads - 1) / threads;
            la_argmax_kernel<<<blocks, threads>>>(index, t, M, N);
        }
        {
            int D4 = D / 4;
            long long total = (long long)N * D4;
            int threads = 256;
            int blocks  = (int)((total + threads - 1) / threads);
            la_gather_generic_kernel<<<blocks, threads>>>((const float4*)msg,
                                                          (float4*)out, N, D4);
        }
    }
}

// round 13
// speedup vs baseline: 1.1535x; 1.0930x over previous
#include <cuda_runtime.h>
#include <cuda_bf16.h>
#include <cstdint>

// ---------------------------------------------------------------------------
// LastAggregator: out[n, :] = msg[argmax_{i : index[i]==n} t[i], :]
// (ties -> smallest i; empty segments -> zeros)
//
//   key(i) = (total_order(t[i]) << 32) | ~i    packed into u64
//   atomicMax over keys per segment  ->  winner = ~(low 32 bits)
//   key == 0  <=>  empty segment (valid keys have nonzero low word).
//
// Two-kernel structure (measured-best): argmax (4 events/thread) then
// gather (2 rows/warp). Self-cleaning: gather resets consumed keys to 0 --
// device-global zero-init covers call 1, every call leaves state clean.
//
// index arrives as int32 (JAX x64 disabled downcasts the declared int64).
// ---------------------------------------------------------------------------

#define MAX_SEGMENTS (1 << 17)  // 131072 >= N = 65536
__device__ unsigned long long g_key[MAX_SEGMENTS];

__device__ __forceinline__ void stcs_f4(float4* p, float4 v) {
    // streaming store: write-once output, evict-first so it never displaces
    // winner rows from L2
    asm volatile("st.global.cs.v4.f32 [%0], {%1,%2,%3,%4};"
                 :: "l"(p), "f"(v.x), "f"(v.y), "f"(v.z), "f"(v.w) : "memory");
}

__device__ __forceinline__ unsigned long long
make_key(float tv, unsigned int i) {
    unsigned int fb  = __float_as_uint(tv);
    unsigned int ord = (fb & 0x80000000u) ? ~fb : (fb | 0x80000000u);
    return ((unsigned long long)ord << 32) | (unsigned long long)(~i);
}

// --- argmax: 4 events per thread, vectorized loads (R6 measured-best) -------
__global__ void la_argmax_kernel(const int* __restrict__ index,
                                 const float* __restrict__ t,
                                 int M, int N) {
    int base = (blockIdx.x * blockDim.x + threadIdx.x) * 4;
    if (base + 3 < M) {
        int4   s  = *reinterpret_cast<const int4*>(index + base);
        float4 tv = *reinterpret_cast<const float4*>(t + base);
        int   segs[4] = {s.x, s.y, s.z, s.w};
        float ts[4]   = {tv.x, tv.y, tv.z, tv.w};
#pragma unroll
        for (int k = 0; k < 4; ++k) {
            unsigned long long key = make_key(ts[k], (unsigned int)(base + k));
            int seg = segs[k];
            if (seg >= 0 && seg < N) atomicMax(&g_key[seg], key);  // -> REDG
        }
    } else {
        for (int i = base; i < M; ++i) {
            unsigned long long key = make_key(t[i], (unsigned int)i);
            int seg = index[i];
            if (seg >= 0 && seg < N) atomicMax(&g_key[seg], key);
        }
    }
}

// --- D=256 gather: one warp per 2 rows (R5 measured-best); self-cleans ------
// Each thread: 4 independent LDG.128 chains + 4 STG.128.
__global__ void la_gather_d256_kernel(const float4* __restrict__ msg,
                                      float4* __restrict__ out,
                                      int N) {
    int gwarp = (blockIdx.x * blockDim.x + threadIdx.x) >> 5;
    int lane  = threadIdx.x & 31;
    int r0 = gwarp * 2;
    int r1 = r0 + 1;
    if (r0 >= N) return;
    bool has1 = (r1 < N);

    // lanes 0/1 fetch the two keys in parallel, broadcast to all lanes
    unsigned long long kk = 0ull;
    if (lane == 0)              kk = g_key[r0];
    else if (lane == 1 && has1) kk = g_key[r1];
    unsigned long long key0 = __shfl_sync(0xffffffffu, kk, 0);
    unsigned long long key1 = __shfl_sync(0xffffffffu, kk, 1);
    // self-clean for next call (after all lanes hold the values)
    if (lane == 0)              g_key[r0] = 0ull;
    else if (lane == 1 && has1) g_key[r1] = 0ull;

    const float4 z = make_float4(0.f, 0.f, 0.f, 0.f);
    size_t ob0 = (size_t)r0 * 64;
    size_t ob1 = (size_t)r1 * 64;

    float4 a0 = z, a1 = z, b0 = z, b1 = z;
    if (key0 != 0ull) {
        size_t ib = (size_t)(~(unsigned int)(key0 & 0xFFFFFFFFull)) * 64;
        a0 = __ldg(&msg[ib + lane]);
        a1 = __ldg(&msg[ib + lane + 32]);
    }
    if (has1 && key1 != 0ull) {
        size_t ib = (size_t)(~(unsigned int)(key1 & 0xFFFFFFFFull)) * 64;
        b0 = __ldg(&msg[ib + lane]);
        b1 = __ldg(&msg[ib + lane + 32]);
    }
    stcs_f4(&out[ob0 + lane],      a0);
    stcs_f4(&out[ob0 + lane + 32], a1);
    if (has1) {
        stcs_f4(&out[ob1 + lane],      b0);
        stcs_f4(&out[ob1 + lane + 32], b1);
    }
}

// --- generic fallback (unexpected D): init + argmax + gather ----------------
__global__ void la_init_kernel(int N) {
    int i = blockIdx.x * blockDim.x + threadIdx.x;
    if (i < N) g_key[i] = 0ull;
}

__global__ void la_gather_generic_kernel(const float4* __restrict__ msg,
                                         float4* __restrict__ out,
                                         int N, int D4) {
    long long e = (long long)blockIdx.x * blockDim.x + threadIdx.x;
    long long total = (long long)N * D4;
    if (e >= total) return;
    int row  = (int)(e / D4);
    int lane = (int)(e % D4);
    unsigned long long key = g_key[row];
    float4 v = make_float4(0.f, 0.f, 0.f, 0.f);
    if (key != 0ull) {
        unsigned int win = ~(unsigned int)(key & 0xFFFFFFFFull);
        v = __ldg(&msg[(size_t)win * D4 + lane]);
    }
    out[(size_t)row * D4 + lane] = v;
}

extern "C" void kernel_launch(void* const* d_in, const int* in_sizes, int n_in,
                              void* d_out, int out_size) {
    // metadata order: msg [M*D f32], index [M i32], t [M f32], (dim_size)
    const float* msg   = (const float*)d_in[0];
    const int*   index = (const int*)d_in[1];
    const float* t     = (const float*)d_in[2];
    float*       out   = (float*)d_out;

    int M = in_sizes[1];              // 262144
    int D = in_sizes[0] / M;          // 256
    int N = out_size / D;             // 65536
    if (N > MAX_SEGMENTS) N = MAX_SEGMENTS;

    if (D == 256) {
        {   // argmax: 4 events/thread (R6 best)
            int threads = 256;
            int per_blk = threads * 4;
            int blocks  = (M + per_blk - 1) / per_blk;
            la_argmax_kernel<<<blocks, threads>>>(index, t, M, N);
        }
        {   // gather: 2 rows per warp (R5 best), self-cleaning
            int threads = 256;                     // 8 warps = 16 rows/block
            int rows_per_blk = (threads / 32) * 2;
            int blocks = (N + rows_per_blk - 1) / rows_per_blk;
            la_gather_d256_kernel<<<blocks, threads>>>((const float4*)msg,
                                                       (float4*)out, N);
        }
    } else {
        // generic safe path
        {
            int threads = 256;
            int blocks  = (N + threads - 1) / threads;
            la_init_kernel<<<blocks, threads>>>(N);
        }
        {
            int threads = 256;
            int per_blk = threads * 4;
            int blocks  = (M + per_blk - 1) / per_blk;
            la_argmax_kernel<<<blocks, threads>>>(index, t, M, N);
        }
        {
            int D4 = D / 4;
            long long total = (long long)N * D4;
            int threads = 256;
            int blocks  = (int)((total + threads - 1) / threads);
            la_gather_generic_kernel<<<blocks, threads>>>((const float4*)msg,
                                                          (float4*)out, N, D4);
        }
    }
}

// round 14
// speedup vs baseline: 1.7222x; 1.4931x over previous
#include <cuda_runtime.h>
#include <cuda_bf16.h>
#include <cstdint>

// ---------------------------------------------------------------------------
// LastAggregator: out[n, :] = msg[argmax_{i : index[i]==n} t[i], :]
// (ties -> smallest i; empty segments -> zeros)
//
//   key(i) = (total_order(t[i]) << 32) | ~i    packed into u64
//   atomicMax over keys per segment  ->  winner = ~(low 32 bits)
//   key == 0  <=>  empty segment (valid keys have nonzero low word).
//
// Two-kernel structure (measured-best): argmax (4 events/thread) then
// gather (2 rows/warp). Self-cleaning: gather resets consumed keys to 0 --
// device-global zero-init covers call 1, every call leaves state clean.
//
// index arrives as int32 (JAX x64 disabled downcasts the declared int64).
// ---------------------------------------------------------------------------

#define MAX_SEGMENTS (1 << 17)  // 131072 >= N = 65536
__device__ unsigned long long g_key[MAX_SEGMENTS];

__device__ __forceinline__ void stcs_f4(float4* p, float4 v) {
    // streaming store: write-once output, evict-first so it never displaces
    // winner rows from L2
    asm volatile("st.global.cs.v4.f32 [%0], {%1,%2,%3,%4};"
                 :: "l"(p), "f"(v.x), "f"(v.y), "f"(v.z), "f"(v.w) : "memory");
}

__device__ __forceinline__ unsigned long long
make_key(float tv, unsigned int i) {
    unsigned int fb  = __float_as_uint(tv);
    unsigned int ord = (fb & 0x80000000u) ? ~fb : (fb | 0x80000000u);
    return ((unsigned long long)ord << 32) | (unsigned long long)(~i);
}

// --- argmax: 4 events per thread, vectorized loads (R6 measured-best) -------
__global__ void la_argmax_kernel(const int* __restrict__ index,
                                 const float* __restrict__ t,
                                 int M, int N) {
    int base = (blockIdx.x * blockDim.x + threadIdx.x) * 4;
    if (base + 3 < M) {
        int4   s  = *reinterpret_cast<const int4*>(index + base);
        float4 tv = *reinterpret_cast<const float4*>(t + base);
        int   segs[4] = {s.x, s.y, s.z, s.w};
        float ts[4]   = {tv.x, tv.y, tv.z, tv.w};
#pragma unroll
        for (int k = 0; k < 4; ++k) {
            unsigned long long key = make_key(ts[k], (unsigned int)(base + k));
            int seg = segs[k];
            if (seg >= 0 && seg < N) atomicMax(&g_key[seg], key);  // -> REDG
        }
    } else {
        for (int i = base; i < M; ++i) {
            unsigned long long key = make_key(t[i], (unsigned int)i);
            int seg = index[i];
            if (seg >= 0 && seg < N) atomicMax(&g_key[seg], key);
        }
    }
}

// --- D=256 gather: one warp per 2 rows; broadcast key loads; self-cleans ----
// Each thread: 4 independent LDG.128 chains + 4 STG.128. Keys are loaded by
// all lanes at a uniform address (L1 broadcast) -- no shfl on the critical path.
__global__ void la_gather_d256_kernel(const float4* __restrict__ msg,
                                      float4* __restrict__ out,
                                      int N) {
    int gwarp = (blockIdx.x * blockDim.x + threadIdx.x) >> 5;
    int lane  = threadIdx.x & 31;
    int r0 = gwarp * 2;
    int r1 = r0 + 1;
    if (r0 >= N) return;
    bool has1 = (r1 < N);

    // uniform-address loads: one broadcast wavefront each, no SHFL chain
    unsigned long long key0 = g_key[r0];
    unsigned long long key1 = has1 ? g_key[r1] : 0ull;
    // self-clean for next call (loads above already issued by whole warp)
    if (lane == 0) {
        g_key[r0] = 0ull;
        if (has1) g_key[r1] = 0ull;
    }

    const float4 z = make_float4(0.f, 0.f, 0.f, 0.f);
    size_t ob0 = (size_t)r0 * 64;
    size_t ob1 = (size_t)r1 * 64;

    float4 a0 = z, a1 = z, b0 = z, b1 = z;
    if (key0 != 0ull) {
        size_t ib = (size_t)(~(unsigned int)(key0 & 0xFFFFFFFFull)) * 64;
        a0 = __ldg(&msg[ib + lane]);
        a1 = __ldg(&msg[ib + lane + 32]);
    }
    if (has1 && key1 != 0ull) {
        size_t ib = (size_t)(~(unsigned int)(key1 & 0xFFFFFFFFull)) * 64;
        b0 = __ldg(&msg[ib + lane]);
        b1 = __ldg(&msg[ib + lane + 32]);
    }
    stcs_f4(&out[ob0 + lane],      a0);
    stcs_f4(&out[ob0 + lane + 32], a1);
    if (has1) {
        stcs_f4(&out[ob1 + lane],      b0);
        stcs_f4(&out[ob1 + lane + 32], b1);
    }
}

// --- generic fallback (unexpected D): init + argmax + gather ----------------
__global__ void la_init_kernel(int N) {
    int i = blockIdx.x * blockDim.x + threadIdx.x;
    if (i < N) g_key[i] = 0ull;
}

__global__ void la_gather_generic_kernel(const float4* __restrict__ msg,
                                         float4* __restrict__ out,
                                         int N, int D4) {
    long long e = (long long)blockIdx.x * blockDim.x + threadIdx.x;
    long long total = (long long)N * D4;
    if (e >= total) return;
    int row  = (int)(e / D4);
    int lane = (int)(e % D4);
    unsigned long long key = g_key[row];
    float4 v = make_float4(0.f, 0.f, 0.f, 0.f);
    if (key != 0ull) {
        unsigned int win = ~(unsigned int)(key & 0xFFFFFFFFull);
        v = __ldg(&msg[(size_t)win * D4 + lane]);
    }
    out[(size_t)row * D4 + lane] = v;
}

extern "C" void kernel_launch(void* const* d_in, const int* in_sizes, int n_in,
                              void* d_out, int out_size) {
    // metadata order: msg [M*D f32], index [M i32], t [M f32], (dim_size)
    const float* msg   = (const float*)d_in[0];
    const int*   index = (const int*)d_in[1];
    const float* t     = (const float*)d_in[2];
    float*       out   = (float*)d_out;

    int M = in_sizes[1];              // 262144
    int D = in_sizes[0] / M;          // 256
    int N = out_size / D;             // 65536
    if (N > MAX_SEGMENTS) N = MAX_SEGMENTS;

    if (D == 256) {
        {   // argmax: 4 events/thread (R6 best)
            int threads = 256;
            int per_blk = threads * 4;
            int blocks  = (M + per_blk - 1) / per_blk;
            la_argmax_kernel<<<blocks, threads>>>(index, t, M, N);
        }
        {   // gather: 2 rows per warp (R5 best), self-cleaning
            int threads = 256;                     // 8 warps = 16 rows/block
            int rows_per_blk = (threads / 32) * 2;
            int blocks = (N + rows_per_blk - 1) / rows_per_blk;
            la_gather_d256_kernel<<<blocks, threads>>>((const float4*)msg,
                                                       (float4*)out, N);
        }
    } else {
        // generic safe path
        {
            int threads = 256;
            int blocks  = (N + threads - 1) / threads;
            la_init_kernel<<<blocks, threads>>>(N);
        }
        {
            int threads = 256;
            int per_blk = threads * 4;
            int blocks  = (M + per_blk - 1) / per_blk;
            la_argmax_kernel<<<blocks, threads>>>(index, t, M, N);
        }
        {
            int D4 = D / 4;
            long long total = (long long)N * D4;
            int threads = 256;
            int blocks  = (int)((total + threads - 1) / threads);
            la_gather_generic_kernel<<<blocks, threads>>>((const float4*)msg,
                                                          (float4*)out, N, D4);
        }
    }
}